// round 1
// baseline (speedup 1.0000x reference)
#include <cuda_runtime.h>
#include <math.h>

// Post_rois: SSD post-processing (decode + softmax scores + greedy NMS + top-200)
// Inputs (metadata order):
//   d_in[0] loc_data   float32 [8, 4096, 4]
//   d_in[1] conf_data  float32 [8*4096, 2]
//   d_in[2] prior_data float32 [4096, 4]   (cx, cy, w, h)
// Output: float32 [8, 2, 200, 5]; class 0 slice all zeros, class 1 = NMS rows.

#define BATCH    8
#define NPRI     4096
#define TOPK     200
#define BLK      512
#define CONF_TH  0.01f
#define NMS_TH   0.45f

// dynamic smem layout:
//   float  skey [NPRI]   16384 B
//   int    sidx [NPRI]   16384 B
//   float4 sbox [NPRI]   65536 B
//   float  sarea[NPRI]   16384 B
#define SMEM_BYTES (NPRI * (4 + 4 + 16 + 4))

__global__ __launch_bounds__(BLK, 1)
void post_rois_kernel(const float* __restrict__ loc,
                      const float* __restrict__ conf,
                      const float* __restrict__ prior,
                      float* __restrict__ out)
{
    const int b   = blockIdx.x;
    const int tid = threadIdx.x;

    extern __shared__ unsigned char smem_raw[];
    float*  skey  = (float*)smem_raw;
    int*    sidx  = (int*)(skey + NPRI);
    float4* sbox  = (float4*)(sidx + NPRI);
    float*  sarea = (float*)(sbox + NPRI);

    __shared__ float4 kbox[TOPK];
    __shared__ float  karea[TOPK];

    // ---- zero this image's output slice (2 * TOPK * 5 floats) ----
    float* ob = out + (size_t)b * 2 * TOPK * 5;
    for (int i = tid; i < 2 * TOPK * 5; i += BLK) ob[i] = 0.0f;

    // ---- phase 1: scores (exact softmax form: exp(x - max) / sum) ----
    for (int n = tid; n < NPRI; n += BLK) {
        float c0 = conf[((size_t)b * NPRI + n) * 2 + 0];
        float c1 = conf[((size_t)b * NPRI + n) * 2 + 1];
        float m  = fmaxf(c0, c1);
        float e0 = expf(__fsub_rn(c0, m));
        float e1 = expf(__fsub_rn(c1, m));
        skey[n] = __fdiv_rn(e1, __fadd_rn(e0, e1));
        sidx[n] = n;
    }
    __syncthreads();

    // ---- phase 2: bitonic sort, descending by score, ties -> ascending idx
    //      (matches stable argsort(-scores)) ----
    for (int k = 2; k <= NPRI; k <<= 1) {
        for (int j = k >> 1; j > 0; j >>= 1) {
            for (int i = tid; i < NPRI; i += BLK) {
                int ixj = i ^ j;
                if (ixj > i) {
                    float s1 = skey[i], s2 = skey[ixj];
                    int   i1 = sidx[i], i2 = sidx[ixj];
                    // before(1,2): element 1 precedes element 2 in final order
                    bool b12 = (s1 > s2) || (s1 == s2 && i1 < i2);
                    bool doswap = ((i & k) == 0) ? (!b12) : b12;
                    if (doswap) {
                        skey[i] = s2; skey[ixj] = s1;
                        sidx[i] = i2; sidx[ixj] = i1;
                    }
                }
            }
            __syncthreads();
        }
    }

    // ---- phase 3: decode boxes into sorted order (pinned IEEE, no FMA) ----
    for (int p = tid; p < NPRI; p += BLK) {
        int n = sidx[p];
        const float* lp = loc + ((size_t)b * NPRI + n) * 4;
        float lx = lp[0], ly = lp[1], lw = lp[2], lh = lp[3];
        float pcx = prior[n * 4 + 0], pcy = prior[n * 4 + 1];
        float pw  = prior[n * 4 + 2], ph  = prior[n * 4 + 3];

        float cx = __fadd_rn(pcx, __fmul_rn(__fmul_rn(lx, 0.1f), pw));
        float cy = __fadd_rn(pcy, __fmul_rn(__fmul_rn(ly, 0.1f), ph));
        float w  = __fmul_rn(pw, expf(__fmul_rn(lw, 0.2f)));
        float h  = __fmul_rn(ph, expf(__fmul_rn(lh, 0.2f)));
        float hw = __fmul_rn(w, 0.5f);
        float hh = __fmul_rn(h, 0.5f);
        float x1 = __fsub_rn(cx, hw), y1 = __fsub_rn(cy, hh);
        float x2 = __fadd_rn(cx, hw), y2 = __fadd_rn(cy, hh);

        sbox[p]  = make_float4(x1, y1, x2, y2);
        sarea[p] = __fmul_rn(__fsub_rn(x2, x1), __fsub_rn(y2, y1));
    }
    __syncthreads();

    // ---- phase 4: greedy NMS vs kept set (early stop at TOPK kept) ----
    // Candidate i is kept iff score > CONF_TH and IoU vs every kept box <= NMS_TH.
    // Thread t checks kept box t; decision broadcast via __syncthreads_or.
    int kept = 0;
    for (int i = 0; i < NPRI && kept < TOPK; i++) {
        float s = skey[i];
        if (!(s > CONF_TH)) break;   // sorted desc: all later candidates invalid too

        float4 bi = sbox[i];
        float  ai = sarea[i];

        bool sup = false;
        if (tid < kept) {
            float4 bj = kbox[tid];
            float iw = fmaxf(__fsub_rn(fminf(bi.z, bj.z), fmaxf(bi.x, bj.x)), 0.0f);
            float ih = fmaxf(__fsub_rn(fminf(bi.w, bj.w), fmaxf(bi.y, bj.y)), 0.0f);
            float inter = __fmul_rn(iw, ih);
            // reference: inter / (area_kept + area_cand - inter)
            float denom = __fsub_rn(__fadd_rn(karea[tid], ai), inter);
            sup = (__fdiv_rn(inter, denom) > NMS_TH);
        }
        if (__syncthreads_or(sup)) continue;   // suppressed by an earlier kept box

        if (tid == 0) {
            kbox[kept]  = bi;
            karea[kept] = ai;
            float* row = ob + (size_t)(TOPK + kept) * 5;  // class-1 slice
            row[0] = s;
            row[1] = bi.x; row[2] = bi.y; row[3] = bi.z; row[4] = bi.w;
        }
        kept++;
        __syncthreads();   // kbox[kept-1] visible before next iteration's reads
    }
}

extern "C" void kernel_launch(void* const* d_in, const int* in_sizes, int n_in,
                              void* d_out, int out_size)
{
    const float* loc   = (const float*)d_in[0];
    const float* conf  = (const float*)d_in[1];
    const float* prior = (const float*)d_in[2];
    float* out = (float*)d_out;

    cudaFuncSetAttribute(post_rois_kernel,
                         cudaFuncAttributeMaxDynamicSharedMemorySize, SMEM_BYTES);
    post_rois_kernel<<<BATCH, BLK, SMEM_BYTES>>>(loc, conf, prior, out);
}